// round 13
// baseline (speedup 1.0000x reference)
#include <cuda_runtime.h>
#include <cuda_fp16.h>
#include <cstdint>

#define MARGIN 0.1f
#define NANF_U 0x7fffffffu
#define INFF_U 0x7f800000u

#define TI 512    // i per block (NI * BI)
#define TJ 64     // j per block
#define BI 256    // threads
#define NI 2      // i rows per thread
#define RT (TI / TJ)   // band width in j-tiles per i-tile row = 8

// Cross-block state; last block resets g_done/g_cnt each launch (graph-safe).
__device__ float        g_part[4096];
__device__ int          g_cnt;
__device__ unsigned int g_done;

__device__ __forceinline__ unsigned hadd2u(unsigned a, unsigned b) {
    unsigned r;
    asm("add.rn.f16x2 %0, %1, %2;" : "=r"(r) : "r"(a), "r"(b));
    return r;
}
// Paired int16 min on the ALU pipe. Valid as fp16 min-vs-positive-constant:
// positives order identically; sign-bit-set values are below +m; positive NaN
// (0x7Exx..0x7FFF) is above +m so m is selected.
__device__ __forceinline__ unsigned mins16x2(unsigned a, unsigned b) {
    unsigned r;
    asm("min.s16x2 %0, %1, %2;" : "=r"(r) : "r"(a), "r"(b));
    return r;
}

// Triangle-tiled sweep (validated R7-R12). fp16x2 body, 2 slots/instr:
//   HADD2 dt, HADD2 dp (fma) | LOP3 sign-fold, MIN.S16X2 (alu) | HADD2 acc (fma)
// Invalid slots are Inf/NaN-folded so dt's sign bit is always 0 there:
//   masked/OOB j -> staged -t = +Inf, -p = +NaN; masked/OOB i -> t = +Inf, p = +NaN
//   => dt = +Inf, s = dp ^ 0 = +NaN -> int16 min picks m. Unmasked diag: dt=+0,
//   s=+0 -> picks 0. Valid: exact min(sign(dt)*dp, m).
// sum_hinge = m_h*(N*N - nv) - A, count = nv*(nv-1), m_h = fp16-exact margin.
__global__ void __launch_bounds__(BI, 7)
mrl_pair(const float* __restrict__ p,
         const float* __restrict__ t,
         const int* __restrict__ m,
         int B, int n64, float* __restrict__ out) {
    // j tile as half: group g of 4 j's = 16B: {t0,t1, p0,p1, t2,t3, p2,p3}
    __shared__ __half sh[TJ * 2];
    __shared__ float red_s[BI / 32];
    __shared__ int   red_c[BI / 32];
    __shared__ int   s_is_last;

    const int tid = threadIdx.x;
    const float NANF = __uint_as_float(NANF_U);
    const float INFF = __uint_as_float(INFF_U);

    // Decode linear block id -> (i-tile r, j-tile). Row r owns n64 - RT*r.
    int bid = blockIdx.x, r = 0, rowcnt;
    while (bid >= (rowcnt = n64 - RT * r)) { bid -= rowcnt; r++; }
    const int i0 = r * TI;
    const int j0 = (RT * r + bid) * TJ;
    const bool band = (j0 < i0 + TI);

    // Stage j tile: valid -> {-t, -p}; masked/OOB -> {+Inf, +NaN}.
    if (tid < TJ) {
        int j = j0 + tid;
        float tj_st = INFF, pj_st = NANF;
        if (j < B && m[j] != 0) {
            tj_st = -t[j];
            pj_st = -p[j];
        }
        int g = tid >> 2, q = tid & 3;
        sh[8 * g + (q >> 1) * 4 + (q & 1)]     = __float2half_rn(tj_st);
        sh[8 * g + (q >> 1) * 4 + (q & 1) + 2] = __float2half_rn(pj_st);
    }
    __syncthreads();

    // i rows: valid -> {t, p}; masked/OOB -> {+Inf, +NaN}. j0==i0 blocks count.
    unsigned ti2[NI], pi2[NI];
    int lcnt = 0;
#pragma unroll
    for (int q = 0; q < NI; q++) {
        int i = i0 + q * BI + tid;
        float tif = INFF, pif = NANF;
        if (i < B && m[i] != 0) { tif = t[i]; pif = p[i]; lcnt++; }
        unsigned th = __half_as_ushort(__float2half_rn(tif));
        unsigned ph = __half_as_ushort(__float2half_rn(pif));
        ti2[q] = th | (th << 16);
        pi2[q] = ph | (ph << 16);
    }
    if (j0 != i0) lcnt = 0;

    const unsigned short mh = __half_as_ushort(__float2half_rn(MARGIN));
    const unsigned m2 = (unsigned)mh | ((unsigned)mh << 16);

    unsigned acc[2 * NI];
#pragma unroll
    for (int k = 0; k < 2 * NI; k++) acc[k] = 0u;

    const uint4* sj4 = reinterpret_cast<const uint4*>(sh);
#pragma unroll
    for (int k = 0; k < TJ / 4; k++) {
        uint4 w = sj4[k];   // {t01, p01, t23, p23} folded halves
#pragma unroll
        for (int q = 0; q < NI; q++) {
            unsigned dta = hadd2u(ti2[q], w.x);
            unsigned dpa = hadd2u(pi2[q], w.y);
            unsigned sa  = dpa ^ (dta & 0x80008000u);
            acc[2 * q] = hadd2u(acc[2 * q], mins16x2(sa, m2));
            unsigned dtb = hadd2u(ti2[q], w.z);
            unsigned dpb = hadd2u(pi2[q], w.w);
            unsigned sb  = dpb ^ (dtb & 0x80008000u);
            acc[2 * q + 1] = hadd2u(acc[2 * q + 1], mins16x2(sb, m2));
        }
    }

    float lsum = 0.f;
#pragma unroll
    for (int k = 0; k < 2 * NI; k++) {
        __half2 a = *reinterpret_cast<__half2*>(&acc[k]);
        lsum += __low2float(a) + __high2float(a);
    }
    if (!band) lsum *= 2.0f;    // strictly-upper tiles stand for both orders

#pragma unroll
    for (int off = 16; off > 0; off >>= 1) {
        lsum += __shfl_down_sync(0xFFFFFFFFu, lsum, off);
        lcnt += __shfl_down_sync(0xFFFFFFFFu, lcnt, off);
    }
    const int wid = tid >> 5, lid = tid & 31;
    if (lid == 0) { red_s[wid] = lsum; red_c[wid] = lcnt; }
    __syncthreads();

    const int nparts = gridDim.x;
    if (wid == 0) {
        constexpr int NW = BI / 32;
        float bs = (lid < NW) ? red_s[lid] : 0.f;
        int   bc = (lid < NW) ? red_c[lid] : 0;
#pragma unroll
        for (int off = 16; off > 0; off >>= 1) {
            bs += __shfl_down_sync(0xFFFFFFFFu, bs, off);
            bc += __shfl_down_sync(0xFFFFFFFFu, bc, off);
        }
        if (lid == 0) {
            g_part[blockIdx.x] = bs;
            if (bc) atomicAdd(&g_cnt, bc);
            __threadfence();
            unsigned int d = atomicAdd(&g_done, 1u);
            s_is_last = (d == (unsigned)(nparts - 1));
        }
    }
    __syncthreads();

    // Last block: reduce partials, apply analytic corrections, reset state.
    if (s_is_last) {
        double s = 0.0;
        for (int k = tid; k < nparts; k += BI) s += (double)g_part[k];
#pragma unroll
        for (int off = 16; off > 0; off >>= 1)
            s += __shfl_down_sync(0xFFFFFFFFu, s, off);
        __shared__ double rds[BI / 32];
        if (lid == 0) rds[wid] = s;
        __syncthreads();
        if (wid == 0) {
            constexpr int NW = BI / 32;
            double bs = (lid < NW) ? rds[lid] : 0.0;
#pragma unroll
            for (int off = 16; off > 0; off >>= 1)
                bs += __shfl_down_sync(0xFFFFFFFFu, bs, off);
            if (lid == 0) {
                double nv = (double)g_cnt;
                double N  = (double)(n64 * TJ);       // padded square dimension
                double mhd = (double)__half2float(__float2half_rn(MARGIN));
                double sum = mhd * (N * N - nv) - bs;
                double cnt = nv * (nv - 1.0);
                if (cnt < 1.0) cnt = 1.0;
                out[0] = (float)(sum / cnt);
                g_done = 0u;   // reset for next graph replay
                g_cnt = 0;
            }
        }
    }
}

extern "C" void kernel_launch(void* const* d_in, const int* in_sizes, int n_in,
                              void* d_out, int out_size) {
    const float* p = (const float*)d_in[0];
    const float* t = (const float*)d_in[1];
    const int*   m = (const int*)d_in[2];
    float* out = (float*)d_out;
    const int B = in_sizes[0];

    const int nt  = (B + TI - 1) / TI;     // i tiles
    const int n64 = nt * RT;               // j tiles across padded width
    int nblocks = 0;
    for (int r = 0; r < nt; r++) nblocks += n64 - RT * r;

    mrl_pair<<<nblocks, BI>>>(p, t, m, B, n64, out);
}

// round 14
// speedup vs baseline: 1.0288x; 1.0288x over previous
#include <cuda_runtime.h>
#include <cuda_fp16.h>
#include <cstdint>

#define MARGIN 0.1f
#define NANF_U 0x7fffffffu
#define INFF_U 0x7f800000u

#define TI 1024   // i per block (NI * BI)
#define TJ 64     // j per block
#define BI 512    // threads
#define NI 2      // i rows per thread
#define RT (TI / TJ)   // band width in j-tiles per i-tile row = 16

// Cross-block state; last block resets g_done/g_cnt each launch (graph-safe).
__device__ float        g_part[4096];
__device__ int          g_cnt;
__device__ unsigned int g_done;

__device__ __forceinline__ unsigned hadd2u(unsigned a, unsigned b) {
    unsigned r;
    asm("add.rn.f16x2 %0, %1, %2;" : "=r"(r) : "r"(a), "r"(b));
    return r;
}
// f16x2 min (minNum: NaN operand -> other operand).
__device__ __forceinline__ unsigned hmin2u(unsigned a, unsigned b) {
    unsigned r;
    asm("min.f16x2 %0, %1, %2;" : "=r"(r) : "r"(a), "r"(b));
    return r;
}

// Triangle-tiled sweep (validated R7-R13). fp16x2 body, 2 slots/instr:
//   HADD2 dt, HADD2 dp, LOP3 sign-fold, HMNMX2 min, HADD2 acc.
// Invalid slots Inf/NaN-folded: masked/OOB j -> staged -t=+Inf, -p=+NaN;
// masked/OOB i -> t=+Inf, p=+NaN => s=+NaN -> min picks m. Unmasked diag:
// dt=+0 -> s=+-0 -> picks 0. Valid: exact min(sign(dt)*dp, m).
// sum_hinge = m_h*(N*N - nv) - A, count = nv*(nv-1), m_h = fp16-exact margin.
__global__ void __launch_bounds__(BI, 4)
mrl_pair(const float* __restrict__ p,
         const float* __restrict__ t,
         const int* __restrict__ m,
         int B, int n64, float* __restrict__ out) {
    // j tile as half: group g of 4 j's = 16B: {t0,t1, p0,p1, t2,t3, p2,p3}
    __shared__ __half sh[TJ * 2];
    __shared__ float red_s[BI / 32];
    __shared__ int   red_c[BI / 32];
    __shared__ int   s_is_last;

    const int tid = threadIdx.x;
    const float NANF = __uint_as_float(NANF_U);
    const float INFF = __uint_as_float(INFF_U);

    // Decode linear block id -> (i-tile r, j-tile). Row r owns n64 - RT*r.
    int bid = blockIdx.x, r = 0, rowcnt;
    while (bid >= (rowcnt = n64 - RT * r)) { bid -= rowcnt; r++; }
    const int i0 = r * TI;
    const int j0 = (RT * r + bid) * TJ;
    const bool band = (j0 < i0 + TI);

    // Stage j tile: valid -> {-t, -p}; masked/OOB -> {+Inf, +NaN}.
    if (tid < TJ) {
        int j = j0 + tid;
        float tj_st = INFF, pj_st = NANF;
        if (j < B && m[j] != 0) {
            tj_st = -t[j];
            pj_st = -p[j];
        }
        int g = tid >> 2, q = tid & 3;
        sh[8 * g + (q >> 1) * 4 + (q & 1)]     = __float2half_rn(tj_st);
        sh[8 * g + (q >> 1) * 4 + (q & 1) + 2] = __float2half_rn(pj_st);
    }
    __syncthreads();

    // i rows: valid -> {t, p}; masked/OOB -> {+Inf, +NaN}. j0==i0 blocks count.
    unsigned ti2[NI], pi2[NI];
    int lcnt = 0;
#pragma unroll
    for (int q = 0; q < NI; q++) {
        int i = i0 + q * BI + tid;
        float tif = INFF, pif = NANF;
        if (i < B && m[i] != 0) { tif = t[i]; pif = p[i]; lcnt++; }
        unsigned th = __half_as_ushort(__float2half_rn(tif));
        unsigned ph = __half_as_ushort(__float2half_rn(pif));
        ti2[q] = th | (th << 16);
        pi2[q] = ph | (ph << 16);
    }
    if (j0 != i0) lcnt = 0;

    const unsigned short mhs = __half_as_ushort(__float2half_rn(MARGIN));
    const unsigned m2 = (unsigned)mhs | ((unsigned)mhs << 16);

    unsigned acc[2 * NI];
#pragma unroll
    for (int k = 0; k < 2 * NI; k++) acc[k] = 0u;

    const uint4* sj4 = reinterpret_cast<const uint4*>(sh);
    uint4 w = sj4[0];
#pragma unroll
    for (int k = 0; k < TJ / 4; k++) {
        uint4 wn;
        if (k + 1 < TJ / 4) wn = sj4[k + 1];   // prefetch next group
#pragma unroll
        for (int q = 0; q < NI; q++) {
            unsigned dta = hadd2u(ti2[q], w.x);
            unsigned dpa = hadd2u(pi2[q], w.y);
            unsigned sa  = dpa ^ (dta & 0x80008000u);
            acc[2 * q] = hadd2u(acc[2 * q], hmin2u(sa, m2));
            unsigned dtb = hadd2u(ti2[q], w.z);
            unsigned dpb = hadd2u(pi2[q], w.w);
            unsigned sb  = dpb ^ (dtb & 0x80008000u);
            acc[2 * q + 1] = hadd2u(acc[2 * q + 1], hmin2u(sb, m2));
        }
        w = wn;
    }

    float lsum = 0.f;
#pragma unroll
    for (int k = 0; k < 2 * NI; k++) {
        __half2 a = *reinterpret_cast<__half2*>(&acc[k]);
        lsum += __low2float(a) + __high2float(a);
    }
    if (!band) lsum *= 2.0f;    // strictly-upper tiles stand for both orders

#pragma unroll
    for (int off = 16; off > 0; off >>= 1) {
        lsum += __shfl_down_sync(0xFFFFFFFFu, lsum, off);
        lcnt += __shfl_down_sync(0xFFFFFFFFu, lcnt, off);
    }
    const int wid = tid >> 5, lid = tid & 31;
    if (lid == 0) { red_s[wid] = lsum; red_c[wid] = lcnt; }
    __syncthreads();

    const int nparts = gridDim.x;
    if (wid == 0) {
        constexpr int NW = BI / 32;
        float bs = (lid < NW) ? red_s[lid] : 0.f;
        int   bc = (lid < NW) ? red_c[lid] : 0;
#pragma unroll
        for (int off = 16; off > 0; off >>= 1) {
            bs += __shfl_down_sync(0xFFFFFFFFu, bs, off);
            bc += __shfl_down_sync(0xFFFFFFFFu, bc, off);
        }
        if (lid == 0) {
            g_part[blockIdx.x] = bs;
            if (bc) atomicAdd(&g_cnt, bc);
            __threadfence();
            unsigned int d = atomicAdd(&g_done, 1u);
            s_is_last = (d == (unsigned)(nparts - 1));
        }
    }
    __syncthreads();

    // Last block: reduce partials, apply analytic corrections, reset state.
    if (s_is_last) {
        double s = 0.0;
        for (int k = tid; k < nparts; k += BI) s += (double)g_part[k];
#pragma unroll
        for (int off = 16; off > 0; off >>= 1)
            s += __shfl_down_sync(0xFFFFFFFFu, s, off);
        __shared__ double rds[BI / 32];
        if (lid == 0) rds[wid] = s;
        __syncthreads();
        if (wid == 0) {
            constexpr int NW = BI / 32;
            double bs = (lid < NW) ? rds[lid] : 0.0;
#pragma unroll
            for (int off = 16; off > 0; off >>= 1)
                bs += __shfl_down_sync(0xFFFFFFFFu, bs, off);
            if (lid == 0) {
                double nv = (double)g_cnt;
                double N  = (double)(n64 * TJ);       // padded square dimension
                double mhd = (double)__half2float(__float2half_rn(MARGIN));
                double sum = mhd * (N * N - nv) - bs;
                double cnt = nv * (nv - 1.0);
                if (cnt < 1.0) cnt = 1.0;
                out[0] = (float)(sum / cnt);
                g_done = 0u;   // reset for next graph replay
                g_cnt = 0;
            }
        }
    }
}

extern "C" void kernel_launch(void* const* d_in, const int* in_sizes, int n_in,
                              void* d_out, int out_size) {
    const float* p = (const float*)d_in[0];
    const float* t = (const float*)d_in[1];
    const int*   m = (const int*)d_in[2];
    float* out = (float*)d_out;
    const int B = in_sizes[0];

    const int nt  = (B + TI - 1) / TI;     // i tiles
    const int n64 = nt * RT;               // j tiles across padded width
    int nblocks = 0;
    for (int r = 0; r < nt; r++) nblocks += n64 - RT * r;

    mrl_pair<<<nblocks, BI>>>(p, t, m, B, n64, out);
}

// round 16
// speedup vs baseline: 1.1629x; 1.1303x over previous
#include <cuda_runtime.h>
#include <cuda_fp16.h>
#include <cstdint>

#define MARGIN 0.1f
#define NANF_U 0x7fffffffu
#define INFF_U 0x7f800000u

#define TI 512    // i per block (NI * BI)
#define TJ 256    // j per block
#define BI 256    // threads
#define NI 2      // i rows per thread
#define RT (TI / TJ)   // band width in j-tiles per i-tile row = 2

// Cross-block state; last block resets g_done/g_cnt each launch (graph-safe).
__device__ float        g_part[4096];
__device__ int          g_cnt;
__device__ unsigned int g_done;

__device__ __forceinline__ unsigned hadd2u(unsigned a, unsigned b) {
    unsigned r;
    asm("add.rn.f16x2 %0, %1, %2;" : "=r"(r) : "r"(a), "r"(b));
    return r;
}
// f16x2 min (minNum: NaN operand -> other operand).
__device__ __forceinline__ unsigned hmin2u(unsigned a, unsigned b) {
    unsigned r;
    asm("min.f16x2 %0, %1, %2;" : "=r"(r) : "r"(a), "r"(b));
    return r;
}

// Triangle-tiled sweep (validated R7-R14). fp16x2 body, 2 slots/instr:
//   HADD2 dt, HADD2 dp, LOP3 sign-fold, HMNMX2 min, HADD2 acc.
// Invalid slots Inf/NaN-folded: masked/OOB j -> staged -t=+Inf, -p=+NaN;
// masked/OOB i -> t=+Inf, p=+NaN => s=+NaN -> min picks m. Unmasked diag:
// dt=+0 -> s=+-0 -> picks 0. Valid: exact min(sign(dt)*dp, m).
// sum_hinge = m_h*(N*N - nv) - A, count = nv*(nv-1), m_h = fp16-exact margin.
__global__ void __launch_bounds__(BI, 7)
mrl_pair(const float* __restrict__ p,
         const float* __restrict__ t,
         const int* __restrict__ m,
         int B, int n64, float* __restrict__ out) {
    // j tile as half: group g of 4 j's = 16B: {t0,t1, p0,p1, t2,t3, p2,p3}
    __shared__ __half sh[TJ * 2];
    __shared__ float red_s[BI / 32];
    __shared__ int   red_c[BI / 32];
    __shared__ int   s_is_last;

    const int tid = threadIdx.x;
    const float NANF = __uint_as_float(NANF_U);
    const float INFF = __uint_as_float(INFF_U);

    // Decode linear block id -> (i-tile r, j-tile). Row r owns n64 - RT*r.
    int bid = blockIdx.x, r = 0, rowcnt;
    while (bid >= (rowcnt = n64 - RT * r)) { bid -= rowcnt; r++; }
    const int i0 = r * TI;
    const int j0 = (RT * r + bid) * TJ;
    const bool band = (j0 < i0 + TI);

    // Stage j tile: valid -> {-t, -p}; masked/OOB -> {+Inf, +NaN}.
    if (tid < TJ) {
        int j = j0 + tid;
        float tj_st = INFF, pj_st = NANF;
        if (j < B && m[j] != 0) {
            tj_st = -t[j];
            pj_st = -p[j];
        }
        int g = tid >> 2, q = tid & 3;
        sh[8 * g + (q >> 1) * 4 + (q & 1)]     = __float2half_rn(tj_st);
        sh[8 * g + (q >> 1) * 4 + (q & 1) + 2] = __float2half_rn(pj_st);
    }
    __syncthreads();

    // i rows: valid -> {t, p}; masked/OOB -> {+Inf, +NaN}. j0==i0 blocks count.
    unsigned ti2[NI], pi2[NI];
    int lcnt = 0;
#pragma unroll
    for (int q = 0; q < NI; q++) {
        int i = i0 + q * BI + tid;
        float tif = INFF, pif = NANF;
        if (i < B && m[i] != 0) { tif = t[i]; pif = p[i]; lcnt++; }
        unsigned th = __half_as_ushort(__float2half_rn(tif));
        unsigned ph = __half_as_ushort(__float2half_rn(pif));
        ti2[q] = th | (th << 16);
        pi2[q] = ph | (ph << 16);
    }
    if (j0 != i0) lcnt = 0;

    const unsigned short mhs = __half_as_ushort(__float2half_rn(MARGIN));
    const unsigned m2 = (unsigned)mhs | ((unsigned)mhs << 16);

    unsigned acc[2 * NI];
#pragma unroll
    for (int k = 0; k < 2 * NI; k++) acc[k] = 0u;

    const uint4* sj4 = reinterpret_cast<const uint4*>(sh);
#pragma unroll 8
    for (int k = 0; k < TJ / 4; k++) {
        uint4 w = sj4[k];   // {t01, p01, t23, p23} folded halves
#pragma unroll
        for (int q = 0; q < NI; q++) {
            unsigned dta = hadd2u(ti2[q], w.x);
            unsigned dpa = hadd2u(pi2[q], w.y);
            unsigned sa  = dpa ^ (dta & 0x80008000u);
            acc[2 * q] = hadd2u(acc[2 * q], hmin2u(sa, m2));
            unsigned dtb = hadd2u(ti2[q], w.z);
            unsigned dpb = hadd2u(pi2[q], w.w);
            unsigned sb  = dpb ^ (dtb & 0x80008000u);
            acc[2 * q + 1] = hadd2u(acc[2 * q + 1], hmin2u(sb, m2));
        }
    }

    float lsum = 0.f;
#pragma unroll
    for (int k = 0; k < 2 * NI; k++) {
        __half2 a = *reinterpret_cast<__half2*>(&acc[k]);
        lsum += __low2float(a) + __high2float(a);
    }
    if (!band) lsum *= 2.0f;    // strictly-upper tiles stand for both orders

#pragma unroll
    for (int off = 16; off > 0; off >>= 1) {
        lsum += __shfl_down_sync(0xFFFFFFFFu, lsum, off);
        lcnt += __shfl_down_sync(0xFFFFFFFFu, lcnt, off);
    }
    const int wid = tid >> 5, lid = tid & 31;
    if (lid == 0) { red_s[wid] = lsum; red_c[wid] = lcnt; }
    __syncthreads();

    const int nparts = gridDim.x;
    if (wid == 0) {
        constexpr int NW = BI / 32;
        float bs = (lid < NW) ? red_s[lid] : 0.f;
        int   bc = (lid < NW) ? red_c[lid] : 0;
#pragma unroll
        for (int off = 16; off > 0; off >>= 1) {
            bs += __shfl_down_sync(0xFFFFFFFFu, bs, off);
            bc += __shfl_down_sync(0xFFFFFFFFu, bc, off);
        }
        if (lid == 0) {
            g_part[blockIdx.x] = bs;
            if (bc) atomicAdd(&g_cnt, bc);
            __threadfence();
            unsigned int d = atomicAdd(&g_done, 1u);
            s_is_last = (d == (unsigned)(nparts - 1));
        }
    }
    __syncthreads();

    // Last block: reduce partials, apply analytic corrections, reset state.
    if (s_is_last) {
        double s = 0.0;
        for (int k = tid; k < nparts; k += BI) s += (double)g_part[k];
#pragma unroll
        for (int off = 16; off > 0; off >>= 1)
            s += __shfl_down_sync(0xFFFFFFFFu, s, off);
        __shared__ double rds[BI / 32];
        if (lid == 0) rds[wid] = s;
        __syncthreads();
        if (wid == 0) {
            constexpr int NW = BI / 32;
            double bs = (lid < NW) ? rds[lid] : 0.0;
#pragma unroll
            for (int off = 16; off > 0; off >>= 1)
                bs += __shfl_down_sync(0xFFFFFFFFu, bs, off);
            if (lid == 0) {
                double nv = (double)g_cnt;
                double N  = (double)(n64 * TJ);       // padded square dimension
                double mhd = (double)__half2float(__float2half_rn(MARGIN));
                double sum = mhd * (N * N - nv) - bs;
                double cnt = nv * (nv - 1.0);
                if (cnt < 1.0) cnt = 1.0;
                out[0] = (float)(sum / cnt);
                g_done = 0u;   // reset for next graph replay
                g_cnt = 0;
            }
        }
    }
}

extern "C" void kernel_launch(void* const* d_in, const int* in_sizes, int n_in,
                              void* d_out, int out_size) {
    const float* p = (const float*)d_in[0];
    const float* t = (const float*)d_in[1];
    const int*   m = (const int*)d_in[2];
    float* out = (float*)d_out;
    const int B = in_sizes[0];

    const int nt  = (B + TI - 1) / TI;     // i tiles
    const int n64 = nt * RT;               // j tiles across padded width
    int nblocks = 0;
    for (int r = 0; r < nt; r++) nblocks += n64 - RT * r;

    mrl_pair<<<nblocks, BI>>>(p, t, m, B, n64, out);
}